// round 5
// baseline (speedup 1.0000x reference)
#include <cuda_runtime.h>
#include <cstdint>
#include <cstddef>

// ---------------------------------------------------------------------------
// hydra_channel_attention: B=8, N=4096, C=E=768
//   h   = LN(x); qkv = h @ w_qkv; phi = l2norm(q|k)
//   kv  = sum_n phi_k * v;  a = LN(phi_q * kv);  out = a @ w_proj
// GEMMs: mma.sync m16n8k8 tf32, 3xTF32 split, 3-stage cp.async pipeline
// with a single __syncthreads per k-tile.
// ---------------------------------------------------------------------------

constexpr int BATCH = 8;
constexpr int NTOK  = 4096;
constexpr int CDIM  = 768;
constexpr int EDIM  = 768;
constexpr int ROWS  = BATCH * NTOK;        // 32768 tokens
constexpr int QKVW  = 3 * EDIM;            // 2304
constexpr int NCHUNK = 8;

// scratch (device globals; no allocations anywhere)
__device__ float g_h_hi [(size_t)ROWS * CDIM];
__device__ float g_h_lo [(size_t)ROWS * CDIM];
__device__ float g_qkv  [(size_t)ROWS * QKVW];
__device__ float g_a_hi [(size_t)ROWS * EDIM];
__device__ float g_a_lo [(size_t)ROWS * EDIM];
__device__ float g_wqkv_hi [(size_t)CDIM * QKVW];
__device__ float g_wqkv_lo [(size_t)CDIM * QKVW];
__device__ float g_wproj_hi[(size_t)EDIM * CDIM];
__device__ float g_wproj_lo[(size_t)EDIM * CDIM];
__device__ float g_invk[ROWS];
__device__ float g_kvpart[NCHUNK * BATCH * EDIM];
__device__ float g_kv  [BATCH * EDIM];

// ---------------------------------------------------------------------------
// helpers
// ---------------------------------------------------------------------------
__device__ __forceinline__ float tf32_round(float x) {
    uint32_t r;
    asm("cvt.rna.tf32.f32 %0, %1;" : "=r"(r) : "f"(x));
    return __uint_as_float(r);
}

__device__ __forceinline__ float2 split_tf32(float x) {
    float h = tf32_round(x);
    float l = tf32_round(x - h);
    return make_float2(h, l);
}

__device__ __forceinline__ void mma_tf32(float c[4],
                                         uint32_t a0, uint32_t a1,
                                         uint32_t a2, uint32_t a3,
                                         uint32_t b0, uint32_t b1) {
    asm volatile(
        "mma.sync.aligned.m16n8k8.row.col.f32.tf32.tf32.f32 "
        "{%0,%1,%2,%3}, {%4,%5,%6,%7}, {%8,%9}, {%0,%1,%2,%3};\n"
        : "+f"(c[0]), "+f"(c[1]), "+f"(c[2]), "+f"(c[3])
        : "r"(a0), "r"(a1), "r"(a2), "r"(a3), "r"(b0), "r"(b1));
}

__device__ __forceinline__ void cp16(uint32_t dst_smem, const float* src) {
    asm volatile("cp.async.cg.shared.global [%0], [%1], 16;\n"
                 :: "r"(dst_smem), "l"(src));
}
__device__ __forceinline__ void cp_commit() {
    asm volatile("cp.async.commit_group;\n");
}
template <int N>
__device__ __forceinline__ void cp_wait() {
    asm volatile("cp.async.wait_group %0;\n" :: "n"(N));
}

__device__ __forceinline__ float2 block_reduce2_192(float a, float b) {
    __shared__ float sa[6], sb[6];
    __syncthreads();
#pragma unroll
    for (int o = 16; o > 0; o >>= 1) {
        a += __shfl_down_sync(0xffffffffu, a, o);
        b += __shfl_down_sync(0xffffffffu, b, o);
    }
    int w = threadIdx.x >> 5;
    if ((threadIdx.x & 31) == 0) { sa[w] = a; sb[w] = b; }
    __syncthreads();
    float ra = 0.f, rb = 0.f;
#pragma unroll
    for (int i = 0; i < 6; ++i) { ra += sa[i]; rb += sb[i]; }
    return make_float2(ra, rb);
}

// ---------------------------------------------------------------------------
// K0: split a weight matrix into tf32 hi/lo
// ---------------------------------------------------------------------------
__global__ __launch_bounds__(256) void wsplit_kernel(
    const float* __restrict__ src,
    float* __restrict__ hi,
    float* __restrict__ lo,
    int n4)
{
    int i = blockIdx.x * 256 + threadIdx.x;
    if (i >= n4) return;
    float4 v = reinterpret_cast<const float4*>(src)[i];
    float4 hv, lv;
    float2 s;
    s = split_tf32(v.x); hv.x = s.x; lv.x = s.y;
    s = split_tf32(v.y); hv.y = s.x; lv.y = s.y;
    s = split_tf32(v.z); hv.z = s.x; lv.z = s.y;
    s = split_tf32(v.w); hv.w = s.x; lv.w = s.y;
    reinterpret_cast<float4*>(hi)[i] = hv;
    reinterpret_cast<float4*>(lo)[i] = lv;
}

// ---------------------------------------------------------------------------
// K1: input LayerNorm -> split hi/lo
// ---------------------------------------------------------------------------
__global__ __launch_bounds__(192) void ln_in_kernel(
    const float* __restrict__ x,
    const float* __restrict__ g,
    const float* __restrict__ b)
{
    const int row = blockIdx.x;
    const int t   = threadIdx.x;
    const float4 v = reinterpret_cast<const float4*>(x + (size_t)row * CDIM)[t];
    float s  = v.x + v.y + v.z + v.w;
    float sq = v.x * v.x + v.y * v.y + v.z * v.z + v.w * v.w;
    float2 r = block_reduce2_192(s, sq);
    const float inv_n = 1.0f / (float)CDIM;
    float mu   = r.x * inv_n;
    float var  = r.y * inv_n - mu * mu;
    float rstd = rsqrtf(var + 1e-5f);
    const float4 gv = reinterpret_cast<const float4*>(g)[t];
    const float4 bv = reinterpret_cast<const float4*>(b)[t];
    float4 o;
    o.x = (v.x - mu) * rstd * gv.x + bv.x;
    o.y = (v.y - mu) * rstd * gv.y + bv.y;
    o.z = (v.z - mu) * rstd * gv.z + bv.z;
    o.w = (v.w - mu) * rstd * gv.w + bv.w;
    float4 hv, lv; float2 sp;
    sp = split_tf32(o.x); hv.x = sp.x; lv.x = sp.y;
    sp = split_tf32(o.y); hv.y = sp.x; lv.y = sp.y;
    sp = split_tf32(o.z); hv.z = sp.x; lv.z = sp.y;
    sp = split_tf32(o.w); hv.w = sp.x; lv.w = sp.y;
    reinterpret_cast<float4*>(g_h_hi + (size_t)row * CDIM)[t] = hv;
    reinterpret_cast<float4*>(g_h_lo + (size_t)row * CDIM)[t] = lv;
}

// ---------------------------------------------------------------------------
// tf32x3 GEMM, 3-stage cp.async pipeline, one barrier per k-tile.
// C[M,N] = (Ahi+Alo)[M,K] @ (Bhi+Blo)[K,N] (3-term), row-major.
// Block 128x128, BK=16, 256 threads = 8 warps (4 M x 2 N), warp 32x64.
// Stage layout: Ahi[128][20], Alo[128][20], Bhi[16][128], Blo[16][128]
// ---------------------------------------------------------------------------
#define TBM 128
#define TBN 128
#define TBK 16
#define AP  20                              // padded A row stride (floats)
#define NSTAGE 3

constexpr int A_FLOATS = TBM * AP;          // 2560
constexpr int B_FLOATS = TBK * TBN;         // 2048
constexpr int STAGE_FLOATS = 2 * A_FLOATS + 2 * B_FLOATS;       // 9216
constexpr int GEMM_SMEM_BYTES = NSTAGE * STAGE_FLOATS * 4;      // 110592

__global__ __launch_bounds__(256, 2) void tf32x3_gemm_kernel(
    const float* __restrict__ Ahi, const float* __restrict__ Alo,
    const float* __restrict__ Bhi, const float* __restrict__ Blo,
    float* __restrict__ C,
    int M, int N, int K)
{
    extern __shared__ float sm[];
    const uint32_t smem_u32 = (uint32_t)__cvta_generic_to_shared(sm);

    const int tid    = threadIdx.x;
    const int lane   = tid & 31;
    const int warpId = tid >> 5;
    const int warpM  = warpId & 3;
    const int warpN  = warpId >> 2;
    const int tg     = lane & 3;
    const int gid    = lane >> 2;

    const int rowBase = blockIdx.y * TBM;
    const int colBase = blockIdx.x * TBN;

    // cp.async per-thread chunk coords (2 chunks per array per tile)
    const int aRow0 = (tid + 0)   >> 2, aQ0 = ((tid + 0)   & 3) * 4;
    const int aRow1 = (tid + 256) >> 2, aQ1 = ((tid + 256) & 3) * 4;
    const int bRow0 = (tid + 0)   >> 5, bQ0 = ((tid + 0)   & 31) * 4;
    const int bRow1 = (tid + 256) >> 5, bQ1 = ((tid + 256) & 31) * 4;

    const float* gAh0 = Ahi + (size_t)(rowBase + aRow0) * K + aQ0;
    const float* gAh1 = Ahi + (size_t)(rowBase + aRow1) * K + aQ1;
    const float* gAl0 = Alo + (size_t)(rowBase + aRow0) * K + aQ0;
    const float* gAl1 = Alo + (size_t)(rowBase + aRow1) * K + aQ1;
    const float* gBh0 = Bhi + (size_t)bRow0 * N + colBase + bQ0;
    const float* gBh1 = Bhi + (size_t)bRow1 * N + colBase + bQ1;
    const float* gBl0 = Blo + (size_t)bRow0 * N + colBase + bQ0;
    const float* gBl1 = Blo + (size_t)bRow1 * N + colBase + bQ1;

    // smem destination offsets (bytes) within a stage
    const uint32_t dAh0 = (aRow0 * AP + aQ0) * 4;
    const uint32_t dAh1 = (aRow1 * AP + aQ1) * 4;
    const uint32_t dAl0 = (A_FLOATS + aRow0 * AP + aQ0) * 4;
    const uint32_t dAl1 = (A_FLOATS + aRow1 * AP + aQ1) * 4;
    const uint32_t dBh0 = (2 * A_FLOATS + bRow0 * TBN + bQ0) * 4;
    const uint32_t dBh1 = (2 * A_FLOATS + bRow1 * TBN + bQ1) * 4;
    const uint32_t dBl0 = (2 * A_FLOATS + B_FLOATS + bRow0 * TBN + bQ0) * 4;
    const uint32_t dBl1 = (2 * A_FLOATS + B_FLOATS + bRow1 * TBN + bQ1) * 4;

    float acc[2][8][4];
#pragma unroll
    for (int i = 0; i < 2; ++i)
#pragma unroll
        for (int j = 0; j < 8; ++j)
#pragma unroll
            for (int l = 0; l < 4; ++l) acc[i][j][l] = 0.f;

    const int NT = K / TBK;                  // 48

    auto issue = [&](int k0, int s) {
        const uint32_t base = smem_u32 + (uint32_t)(s * STAGE_FLOATS * 4);
        size_t kb = (size_t)k0 * N;
        cp16(base + dAh0, gAh0 + k0);
        cp16(base + dAh1, gAh1 + k0);
        cp16(base + dAl0, gAl0 + k0);
        cp16(base + dAl1, gAl1 + k0);
        cp16(base + dBh0, gBh0 + kb);
        cp16(base + dBh1, gBh1 + kb);
        cp16(base + dBl0, gBl0 + kb);
        cp16(base + dBl1, gBl1 + kb);
        cp_commit();
    };

    // prologue: stages 0 and 1 in flight
    issue(0, 0);
    issue(TBK, 1);

    int buf = 0;
    for (int t = 0; t < NT; ++t) {
        // retire exactly tile t (tile t+1 stays in flight through compute)
        if (t + 1 < NT) cp_wait<1>(); else cp_wait<0>();
        __syncthreads();   // publish tile t; also proves buffer (t+2)%3 drained

        if (t + 2 < NT) issue((t + 2) * TBK, (buf + 2) % NSTAGE);

        const float* sAh = sm + buf * STAGE_FLOATS;
        const float* sAl = sAh + A_FLOATS;
        const float* sBh = sAh + 2 * A_FLOATS;
        const float* sBl = sBh + B_FLOATS;

#pragma unroll
        for (int kk = 0; kk < TBK; kk += 8) {
            uint32_t ah[2][4], al[2][4];
#pragma unroll
            for (int ma = 0; ma < 2; ++ma) {
                int m = warpM * 32 + ma * 16 + gid;
                ah[ma][0] = __float_as_uint(sAh[(m)     * AP + kk + tg]);
                ah[ma][1] = __float_as_uint(sAh[(m + 8) * AP + kk + tg]);
                ah[ma][2] = __float_as_uint(sAh[(m)     * AP + kk + tg + 4]);
                ah[ma][3] = __float_as_uint(sAh[(m + 8) * AP + kk + tg + 4]);
                al[ma][0] = __float_as_uint(sAl[(m)     * AP + kk + tg]);
                al[ma][1] = __float_as_uint(sAl[(m + 8) * AP + kk + tg]);
                al[ma][2] = __float_as_uint(sAl[(m)     * AP + kk + tg + 4]);
                al[ma][3] = __float_as_uint(sAl[(m + 8) * AP + kk + tg + 4]);
            }
#pragma unroll
            for (int na = 0; na < 8; ++na) {
                int n = warpN * 64 + na * 8 + gid;
                uint32_t bh0 = __float_as_uint(sBh[(kk + tg)     * TBN + n]);
                uint32_t bh1 = __float_as_uint(sBh[(kk + tg + 4) * TBN + n]);
                uint32_t bl0 = __float_as_uint(sBl[(kk + tg)     * TBN + n]);
                uint32_t bl1 = __float_as_uint(sBl[(kk + tg + 4) * TBN + n]);
#pragma unroll
                for (int ma = 0; ma < 2; ++ma) {
                    mma_tf32(acc[ma][na], ah[ma][0], ah[ma][1], ah[ma][2], ah[ma][3],
                             bh0, bh1);
                    mma_tf32(acc[ma][na], ah[ma][0], ah[ma][1], ah[ma][2], ah[ma][3],
                             bl0, bl1);
                    mma_tf32(acc[ma][na], al[ma][0], al[ma][1], al[ma][2], al[ma][3],
                             bh0, bh1);
                }
            }
        }
        buf = (buf + 1) % NSTAGE;
    }

    // ---- epilogue ----
#pragma unroll
    for (int ma = 0; ma < 2; ++ma) {
        int r0 = rowBase + warpM * 32 + ma * 16 + gid;
#pragma unroll
        for (int na = 0; na < 8; ++na) {
            int col = colBase + warpN * 64 + na * 8 + tg * 2;
            *reinterpret_cast<float2*>(C + (size_t)r0 * N + col) =
                make_float2(acc[ma][na][0], acc[ma][na][1]);
            *reinterpret_cast<float2*>(C + (size_t)(r0 + 8) * N + col) =
                make_float2(acc[ma][na][2], acc[ma][na][3]);
        }
    }
}

// ---------------------------------------------------------------------------
// K3: per-token 1/max(||k||, 1e-12)
// ---------------------------------------------------------------------------
__global__ __launch_bounds__(192) void invk_kernel()
{
    const int row = blockIdx.x;
    const int t   = threadIdx.x;
    const float4 v =
        reinterpret_cast<const float4*>(g_qkv + (size_t)row * QKVW + EDIM)[t];
    float sq = v.x * v.x + v.y * v.y + v.z * v.z + v.w * v.w;
    float2 r = block_reduce2_192(sq, 0.f);
    if (t == 0) g_invk[row] = 1.0f / fmaxf(sqrtf(r.x), 1e-12f);
}

// ---------------------------------------------------------------------------
// K4: partial kv over 512-token chunks (fixed-order, deterministic)
// ---------------------------------------------------------------------------
__global__ __launch_bounds__(512) void kvpart_kernel()
{
    const int el = threadIdx.x & 63;
    const int ng = threadIdx.x >> 6;
    const int e  = blockIdx.x * 64 + el;
    const int b  = blockIdx.z;
    const int nBase = blockIdx.y * 512;

    float s = 0.f;
#pragma unroll 4
    for (int i = 0; i < 64; ++i) {
        int n = nBase + i * 8 + ng;
        size_t row = (size_t)b * NTOK + n;
        const float* p = g_qkv + row * QKVW;
        s += p[EDIM + e] * g_invk[row] * p[2 * EDIM + e];
    }
    __shared__ float red[8][64];
    red[ng][el] = s;
    __syncthreads();
    if (ng == 0) {
        float tot = 0.f;
#pragma unroll
        for (int c = 0; c < 8; ++c) tot += red[c][el];
        g_kvpart[(blockIdx.y * BATCH + b) * EDIM + e] = tot;
    }
}

__global__ __launch_bounds__(256) void kvreduce_kernel()
{
    int idx = blockIdx.x * 256 + threadIdx.x;
    if (idx < BATCH * EDIM) {
        float s = 0.f;
#pragma unroll
        for (int c = 0; c < NCHUNK; ++c) s += g_kvpart[c * BATCH * EDIM + idx];
        g_kv[idx] = s;
    }
}

// ---------------------------------------------------------------------------
// K6: fused invq + attn + output LayerNorm -> split hi/lo
// ---------------------------------------------------------------------------
__global__ __launch_bounds__(192) void attn_ln_kernel(
    const float* __restrict__ g,
    const float* __restrict__ b)
{
    const int row = blockIdx.x;
    const int bat = row >> 12;
    const int t   = threadIdx.x;

    const float4 q =
        reinterpret_cast<const float4*>(g_qkv + (size_t)row * QKVW)[t];
    float sq = q.x * q.x + q.y * q.y + q.z * q.z + q.w * q.w;
    float2 r1 = block_reduce2_192(sq, 0.f);
    float invq = 1.0f / fmaxf(sqrtf(r1.x), 1e-12f);

    const float4 kv = reinterpret_cast<const float4*>(g_kv + bat * EDIM)[t];
    float4 tv;
    tv.x = q.x * invq * kv.x;
    tv.y = q.y * invq * kv.y;
    tv.z = q.z * invq * kv.z;
    tv.w = q.w * invq * kv.w;

    float s   = tv.x + tv.y + tv.z + tv.w;
    float sq2 = tv.x * tv.x + tv.y * tv.y + tv.z * tv.z + tv.w * tv.w;
    float2 r2 = block_reduce2_192(s, sq2);
    const float inv_n = 1.0f / (float)EDIM;
    float mu   = r2.x * inv_n;
    float var  = r2.y * inv_n - mu * mu;
    float rstd = rsqrtf(var + 1e-5f);

    const float4 gv = reinterpret_cast<const float4*>(g)[t];
    const float4 bv = reinterpret_cast<const float4*>(b)[t];
    float4 o;
    o.x = (tv.x - mu) * rstd * gv.x + bv.x;
    o.y = (tv.y - mu) * rstd * gv.y + bv.y;
    o.z = (tv.z - mu) * rstd * gv.z + bv.z;
    o.w = (tv.w - mu) * rstd * gv.w + bv.w;
    float4 hv, lv; float2 sp;
    sp = split_tf32(o.x); hv.x = sp.x; lv.x = sp.y;
    sp = split_tf32(o.y); hv.y = sp.x; lv.y = sp.y;
    sp = split_tf32(o.z); hv.z = sp.x; lv.z = sp.y;
    sp = split_tf32(o.w); hv.w = sp.x; lv.w = sp.y;
    reinterpret_cast<float4*>(g_a_hi + (size_t)row * EDIM)[t] = hv;
    reinterpret_cast<float4*>(g_a_lo + (size_t)row * EDIM)[t] = lv;
}

// ---------------------------------------------------------------------------
// Launch
// ---------------------------------------------------------------------------
extern "C" void kernel_launch(void* const* d_in, const int* in_sizes, int n_in,
                              void* d_out, int out_size)
{
    (void)in_sizes; (void)n_in; (void)out_size;
    const float* x        = (const float*)d_in[0];
    const float* w_qkv    = (const float*)d_in[1];
    const float* w_proj   = (const float*)d_in[2];
    const float* ln_in_g  = (const float*)d_in[3];
    const float* ln_in_b  = (const float*)d_in[4];
    const float* ln_out_g = (const float*)d_in[5];
    const float* ln_out_b = (const float*)d_in[6];
    float* out = (float*)d_out;

    void *phh, *phl, *pqkv, *pah, *pal, *pwqh, *pwql, *pwph, *pwpl;
    cudaGetSymbolAddress(&phh,  g_h_hi);
    cudaGetSymbolAddress(&phl,  g_h_lo);
    cudaGetSymbolAddress(&pqkv, g_qkv);
    cudaGetSymbolAddress(&pah,  g_a_hi);
    cudaGetSymbolAddress(&pal,  g_a_lo);
    cudaGetSymbolAddress(&pwqh, g_wqkv_hi);
    cudaGetSymbolAddress(&pwql, g_wqkv_lo);
    cudaGetSymbolAddress(&pwph, g_wproj_hi);
    cudaGetSymbolAddress(&pwpl, g_wproj_lo);

    cudaFuncSetAttribute(tf32x3_gemm_kernel,
                         cudaFuncAttributeMaxDynamicSharedMemorySize,
                         GEMM_SMEM_BYTES);

    {
        int n4 = CDIM * QKVW / 4;
        wsplit_kernel<<<(n4 + 255) / 256, 256>>>(w_qkv, (float*)pwqh, (float*)pwql, n4);
        n4 = EDIM * CDIM / 4;
        wsplit_kernel<<<(n4 + 255) / 256, 256>>>(w_proj, (float*)pwph, (float*)pwpl, n4);
    }

    ln_in_kernel<<<ROWS, 192>>>(x, ln_in_g, ln_in_b);

    tf32x3_gemm_kernel<<<dim3(QKVW / TBN, ROWS / TBM), 256, GEMM_SMEM_BYTES>>>(
        (const float*)phh, (const float*)phl,
        (const float*)pwqh, (const float*)pwql,
        (float*)pqkv, ROWS, QKVW, CDIM);

    invk_kernel<<<ROWS, 192>>>();

    kvpart_kernel<<<dim3(EDIM / 64, NTOK / 512, BATCH), 512>>>();

    kvreduce_kernel<<<(BATCH * EDIM + 255) / 256, 256>>>();

    attn_ln_kernel<<<ROWS, 192>>>(ln_out_g, ln_out_b);

    tf32x3_gemm_kernel<<<dim3(EDIM / TBN, ROWS / TBM), 256, GEMM_SMEM_BYTES>>>(
        (const float*)pah, (const float*)pal,
        (const float*)pwph, (const float*)pwpl,
        out, ROWS, EDIM, CDIM);
}

// round 6
// speedup vs baseline: 1.4442x; 1.4442x over previous
#include <cuda_runtime.h>
#include <cstdint>
#include <cstddef>

// ---------------------------------------------------------------------------
// hydra_channel_attention: B=8, N=4096, C=E=768
// GEMMs: mma.sync m16n8k8 tf32x3, fragment-packed operand layouts:
//   A packed: per (rowblk 128)x(ktile 16): [mg(8)][kk(2)][lane(32)] float4
//             float4 = {A[m][k], A[m+8][k], A[m][k+4], A[m+8][k+4]},
//             m = mg*16+gid, k = kk*8+tg, lane = gid*4+tg
//   B packed: per (colblk 128)x(ktile 16): [ng(16)][kk(2)][lane(32)] float4
//             float4 = {Bhi[k][n], Bhi[k+4][n], Blo[k][n], Blo[k+4][n]},
//             n = ng*8+gid, k = kk*8+tg
// -> all fragment reads are single conflict-free LDS.128.
// ---------------------------------------------------------------------------

constexpr int BATCH = 8;
constexpr int NTOK  = 4096;
constexpr int CDIM  = 768;
constexpr int EDIM  = 768;
constexpr int ROWS  = BATCH * NTOK;        // 32768
constexpr int QKVW  = 3 * EDIM;            // 2304
constexpr int NCHUNK = 8;
constexpr int NKT   = 48;                  // K/16 for both GEMMs (K=768)

// scratch (device globals; no allocations anywhere)
__device__ float g_h_hi [(size_t)ROWS * CDIM];    // packed A (hi) for GEMM1
__device__ float g_h_lo [(size_t)ROWS * CDIM];    // packed A (lo)
__device__ float g_qkv  [(size_t)ROWS * QKVW];    // row-major
__device__ float g_a_hi [(size_t)ROWS * EDIM];    // packed A (hi) for GEMM2
__device__ float g_a_lo [(size_t)ROWS * EDIM];
__device__ float g_wqkv_pk [(size_t)2 * CDIM * QKVW];   // packed B (hi|lo)
__device__ float g_wproj_pk[(size_t)2 * EDIM * CDIM];
__device__ float g_invk[ROWS];
__device__ float g_kvpart[NCHUNK * BATCH * EDIM];
__device__ float g_kv  [BATCH * EDIM];

// ---------------------------------------------------------------------------
// helpers
// ---------------------------------------------------------------------------
__device__ __forceinline__ float tf32_round(float x) {
    uint32_t r;
    asm("cvt.rna.tf32.f32 %0, %1;" : "=r"(r) : "f"(x));
    return __uint_as_float(r);
}
__device__ __forceinline__ float2 split_tf32(float x) {
    float h = tf32_round(x);
    float l = tf32_round(x - h);
    return make_float2(h, l);
}
__device__ __forceinline__ void mma_tf32(float c[4],
                                         uint32_t a0, uint32_t a1,
                                         uint32_t a2, uint32_t a3,
                                         uint32_t b0, uint32_t b1) {
    asm volatile(
        "mma.sync.aligned.m16n8k8.row.col.f32.tf32.tf32.f32 "
        "{%0,%1,%2,%3}, {%4,%5,%6,%7}, {%8,%9}, {%0,%1,%2,%3};\n"
        : "+f"(c[0]), "+f"(c[1]), "+f"(c[2]), "+f"(c[3])
        : "r"(a0), "r"(a1), "r"(a2), "r"(a3), "r"(b0), "r"(b1));
}
__device__ __forceinline__ void cp16(uint32_t dst_smem, const float* src) {
    asm volatile("cp.async.cg.shared.global [%0], [%1], 16;\n"
                 :: "r"(dst_smem), "l"(src));
}
__device__ __forceinline__ void cp_commit() {
    asm volatile("cp.async.commit_group;\n");
}
template <int N>
__device__ __forceinline__ void cp_wait() {
    asm volatile("cp.async.wait_group %0;\n" :: "n"(N));
}

__device__ __forceinline__ float warp_sum(float v) {
#pragma unroll
    for (int o = 16; o > 0; o >>= 1) v += __shfl_xor_sync(0xffffffffu, v, o);
    return v;
}

__device__ __forceinline__ float2 block_reduce2_192(float a, float b) {
    __shared__ float sa[6], sb[6];
    __syncthreads();
#pragma unroll
    for (int o = 16; o > 0; o >>= 1) {
        a += __shfl_down_sync(0xffffffffu, a, o);
        b += __shfl_down_sync(0xffffffffu, b, o);
    }
    int w = threadIdx.x >> 5;
    if ((threadIdx.x & 31) == 0) { sa[w] = a; sb[w] = b; }
    __syncthreads();
    float ra = 0.f, rb = 0.f;
#pragma unroll
    for (int i = 0; i < 6; ++i) { ra += sa[i]; rb += sb[i]; }
    return make_float2(ra, rb);
}

// ---------------------------------------------------------------------------
// K0: weight split + pack into fragment layout.
// Output float4 idx: ((cb*NKT + kt)*1024) + (ng*2+kk)*32 + lane
// ---------------------------------------------------------------------------
__global__ __launch_bounds__(256) void wsplit_pack_kernel(
    const float* __restrict__ w, float* __restrict__ pk, int N, int nf4)
{
    int idx = blockIdx.x * 256 + threadIdx.x;
    if (idx >= nf4) return;
    int lane = idx & 31;
    int kk   = (idx >> 5) & 1;
    int ng   = (idx >> 6) & 15;
    int t2   = idx >> 10;
    int kt   = t2 % NKT;
    int cb   = t2 / NKT;
    int gid  = lane >> 2, tg = lane & 3;
    int k0   = kt * 16 + kk * 8;
    int n    = cb * 128 + ng * 8 + gid;
    float va = w[(size_t)(k0 + tg)     * N + n];
    float vb = w[(size_t)(k0 + tg + 4) * N + n];
    float2 sa = split_tf32(va);
    float2 sb = split_tf32(vb);
    reinterpret_cast<float4*>(pk)[idx] = make_float4(sa.x, sb.x, sa.y, sb.y);
}

// ---------------------------------------------------------------------------
// K1: input LayerNorm -> split -> packed A layout.
// Block = 16 rows (one mg group), 512 threads.
// ---------------------------------------------------------------------------
__global__ __launch_bounds__(512) void ln_in_pack_kernel(
    const float* __restrict__ x,
    const float* __restrict__ g,
    const float* __restrict__ b)
{
    __shared__ float s_mu[16], s_rs[16];
    const int tid = threadIdx.x, w = tid >> 5, lane = tid & 31;
    const size_t rowBase = (size_t)blockIdx.x * 16;

    // phase 1: per-row LN stats (warp w -> local row w), fixed-order reduce
    {
        const float* xr = x + (rowBase + w) * CDIM;
        float s = 0.f, q = 0.f;
#pragma unroll
        for (int j = 0; j < 24; ++j) {
            float v = xr[lane + 32 * j];
            s += v; q += v * v;
        }
        s = warp_sum(s); q = warp_sum(q);
        if (lane == 0) {
            float mu  = s * (1.f / 768.f);
            float var = q * (1.f / 768.f) - mu * mu;
            s_mu[w] = mu;
            s_rs[w] = rsqrtf(var + 1e-5f);
        }
    }
    __syncthreads();

    // phase 2: normalize + split + packed write
    const int rb = blockIdx.x >> 3, mg = blockIdx.x & 7;
    float4* H = reinterpret_cast<float4*>(g_h_hi);
    float4* L = reinterpret_cast<float4*>(g_h_lo);
    for (int i = tid; i < 768; i += 512) {
        int gid = i & 7, kk = (i >> 3) & 1, kt = i >> 4;
        int k0 = kt * 16 + kk * 8;
        const float* r0 = x + (rowBase + gid) * CDIM + k0;
        const float* r1 = r0 + 8 * CDIM;
        float a0[8], a1[8], gv[8], bv[8];
        *reinterpret_cast<float4*>(a0)     = *reinterpret_cast<const float4*>(r0);
        *reinterpret_cast<float4*>(a0 + 4) = *reinterpret_cast<const float4*>(r0 + 4);
        *reinterpret_cast<float4*>(a1)     = *reinterpret_cast<const float4*>(r1);
        *reinterpret_cast<float4*>(a1 + 4) = *reinterpret_cast<const float4*>(r1 + 4);
        *reinterpret_cast<float4*>(gv)     = *reinterpret_cast<const float4*>(g + k0);
        *reinterpret_cast<float4*>(gv + 4) = *reinterpret_cast<const float4*>(g + k0 + 4);
        *reinterpret_cast<float4*>(bv)     = *reinterpret_cast<const float4*>(b + k0);
        *reinterpret_cast<float4*>(bv + 4) = *reinterpret_cast<const float4*>(b + k0 + 4);
        float mu0 = s_mu[gid], rs0 = s_rs[gid];
        float mu1 = s_mu[gid + 8], rs1 = s_rs[gid + 8];
        float h0[8], l0[8], h1[8], l1[8];
#pragma unroll
        for (int j = 0; j < 8; ++j) {
            float2 sp;
            sp = split_tf32((a0[j] - mu0) * rs0 * gv[j] + bv[j]);
            h0[j] = sp.x; l0[j] = sp.y;
            sp = split_tf32((a1[j] - mu1) * rs1 * gv[j] + bv[j]);
            h1[j] = sp.x; l1[j] = sp.y;
        }
        size_t base = ((size_t)(rb * NKT + kt)) * 512 + (mg * 2 + kk) * 32 + gid * 4;
#pragma unroll
        for (int tg = 0; tg < 4; ++tg) {
            H[base + tg] = make_float4(h0[tg], h1[tg], h0[tg + 4], h1[tg + 4]);
            L[base + tg] = make_float4(l0[tg], l1[tg], l0[tg + 4], l1[tg + 4]);
        }
    }
}

// ---------------------------------------------------------------------------
// tf32x3 GEMM on packed operands. C[M,N] row-major.
// Block 128x128, BK=16, 256 threads, 3-stage cp.async, 1 barrier per tile.
// Stage = Ahi(2048f) | Alo(2048f) | Bpk(4096f) = 32KB.
// ---------------------------------------------------------------------------
constexpr int STAGE_FLOATS = 8192;
constexpr int GEMM_SMEM_BYTES = 3 * STAGE_FLOATS * 4;   // 98304

__global__ __launch_bounds__(256, 2) void tf32x3_gemm_pk_kernel(
    const float* __restrict__ Ahi, const float* __restrict__ Alo,
    const float* __restrict__ Bpk, float* __restrict__ C, int N)
{
    extern __shared__ float sm[];
    const uint32_t smem_u32 = (uint32_t)__cvta_generic_to_shared(sm);

    const int tid    = threadIdx.x;
    const int lane   = tid & 31;
    const int warpId = tid >> 5;
    const int warpM  = warpId & 3;
    const int warpN  = warpId >> 2;
    const int tg     = lane & 3;
    const int gid    = lane >> 2;

    const int rb = blockIdx.y, cb = blockIdx.x;

    const float* gAh = Ahi + (size_t)rb * NKT * 2048;
    const float* gAl = Alo + (size_t)rb * NKT * 2048;
    const float* gB  = Bpk + (size_t)cb * NKT * 4096;

    float acc[2][8][4];
#pragma unroll
    for (int i = 0; i < 2; ++i)
#pragma unroll
        for (int j = 0; j < 8; ++j)
#pragma unroll
            for (int l = 0; l < 4; ++l) acc[i][j][l] = 0.f;

    auto issue = [&](int kt, int s) {
        const uint32_t base = smem_u32 + (uint32_t)(s * STAGE_FLOATS * 4);
        const float* ah = gAh + kt * 2048;
        const float* al = gAl + kt * 2048;
        const float* bp = gB  + kt * 4096;
#pragma unroll
        for (int j = 0; j < 2; ++j) {
            int c4 = tid + 256 * j;
            cp16(base + c4 * 16,         ah + c4 * 4);
            cp16(base + 8192 + c4 * 16,  al + c4 * 4);
        }
#pragma unroll
        for (int j = 0; j < 4; ++j) {
            int c4 = tid + 256 * j;
            cp16(base + 16384 + c4 * 16, bp + c4 * 4);
        }
        cp_commit();
    };

    issue(0, 0);
    issue(1, 1);

    int buf = 0;
    for (int t = 0; t < NKT; ++t) {
        if (t + 1 < NKT) cp_wait<1>(); else cp_wait<0>();
        __syncthreads();   // publish tile t; proves buffer (t+2)%3 drained

        if (t + 2 < NKT) issue(t + 2, (buf + 2) % 3);

        const float4* sAh = reinterpret_cast<const float4*>(sm + buf * STAGE_FLOATS);
        const float4* sAl = sAh + 512;
        const float4* sB  = sAh + 1024;

#pragma unroll
        for (int kk = 0; kk < 2; ++kk) {
            float4 ah[2], al[2];
#pragma unroll
            for (int ma = 0; ma < 2; ++ma) {
                int fi = ((warpM * 2 + ma) * 2 + kk) * 32 + lane;
                ah[ma] = sAh[fi];
                al[ma] = sAl[fi];
            }
#pragma unroll
            for (int na = 0; na < 8; ++na) {
                float4 bv = sB[((warpN * 8 + na) * 2 + kk) * 32 + lane];
                uint32_t bh0 = __float_as_uint(bv.x), bh1 = __float_as_uint(bv.y);
                uint32_t bl0 = __float_as_uint(bv.z), bl1 = __float_as_uint(bv.w);
#pragma unroll
                for (int ma = 0; ma < 2; ++ma) {
                    uint32_t a0 = __float_as_uint(ah[ma].x), a1 = __float_as_uint(ah[ma].y);
                    uint32_t a2 = __float_as_uint(ah[ma].z), a3 = __float_as_uint(ah[ma].w);
                    uint32_t c0 = __float_as_uint(al[ma].x), c1 = __float_as_uint(al[ma].y);
                    uint32_t c2 = __float_as_uint(al[ma].z), c3 = __float_as_uint(al[ma].w);
                    mma_tf32(acc[ma][na], a0, a1, a2, a3, bh0, bh1);
                    mma_tf32(acc[ma][na], a0, a1, a2, a3, bl0, bl1);
                    mma_tf32(acc[ma][na], c0, c1, c2, c3, bh0, bh1);
                }
            }
        }
        buf = (buf + 1) % 3;
    }

    // epilogue
#pragma unroll
    for (int ma = 0; ma < 2; ++ma) {
        int r0 = rb * 128 + warpM * 32 + ma * 16 + gid;
#pragma unroll
        for (int na = 0; na < 8; ++na) {
            int col = cb * 128 + warpN * 64 + na * 8 + tg * 2;
            *reinterpret_cast<float2*>(C + (size_t)r0 * N + col) =
                make_float2(acc[ma][na][0], acc[ma][na][1]);
            *reinterpret_cast<float2*>(C + (size_t)(r0 + 8) * N + col) =
                make_float2(acc[ma][na][2], acc[ma][na][3]);
        }
    }
}

// ---------------------------------------------------------------------------
// K3: per-token 1/max(||k||, 1e-12)
// ---------------------------------------------------------------------------
__global__ __launch_bounds__(192) void invk_kernel()
{
    const int row = blockIdx.x;
    const int t   = threadIdx.x;
    const float4 v =
        reinterpret_cast<const float4*>(g_qkv + (size_t)row * QKVW + EDIM)[t];
    float sq = v.x * v.x + v.y * v.y + v.z * v.z + v.w * v.w;
    float2 r = block_reduce2_192(sq, 0.f);
    if (t == 0) g_invk[row] = 1.0f / fmaxf(sqrtf(r.x), 1e-12f);
}

// ---------------------------------------------------------------------------
// K4: partial kv over 512-token chunks (fixed-order, deterministic)
// ---------------------------------------------------------------------------
__global__ __launch_bounds__(512) void kvpart_kernel()
{
    const int el = threadIdx.x & 63;
    const int ng = threadIdx.x >> 6;
    const int e  = blockIdx.x * 64 + el;
    const int b  = blockIdx.z;
    const int nBase = blockIdx.y * 512;

    float s = 0.f;
#pragma unroll 4
    for (int i = 0; i < 64; ++i) {
        int n = nBase + i * 8 + ng;
        size_t row = (size_t)b * NTOK + n;
        const float* p = g_qkv + row * QKVW;
        s += p[EDIM + e] * g_invk[row] * p[2 * EDIM + e];
    }
    __shared__ float red[8][64];
    red[ng][el] = s;
    __syncthreads();
    if (ng == 0) {
        float tot = 0.f;
#pragma unroll
        for (int c = 0; c < 8; ++c) tot += red[c][el];
        g_kvpart[(blockIdx.y * BATCH + b) * EDIM + e] = tot;
    }
}

__global__ __launch_bounds__(256) void kvreduce_kernel()
{
    int idx = blockIdx.x * 256 + threadIdx.x;
    if (idx < BATCH * EDIM) {
        float s = 0.f;
#pragma unroll
        for (int c = 0; c < NCHUNK; ++c) s += g_kvpart[c * BATCH * EDIM + idx];
        g_kv[idx] = s;
    }
}

// ---------------------------------------------------------------------------
// K6: fused invq + attn + output LayerNorm -> split -> packed A layout.
// Block = 16 rows, 512 threads. Phase1 stores (invq, mu, rstd) per row;
// phase2 recomputes tv elementwise (identical arithmetic -> deterministic).
// ---------------------------------------------------------------------------
__global__ __launch_bounds__(512) void attn_ln_pack_kernel(
    const float* __restrict__ g,
    const float* __restrict__ b)
{
    __shared__ float s_iq[16], s_mu[16], s_rs[16];
    const int tid = threadIdx.x, w = tid >> 5, lane = tid & 31;
    const size_t rowBase = (size_t)blockIdx.x * 16;
    const int bat = (int)(rowBase >> 12);
    const float* kvp = g_kv + bat * EDIM;

    // phase 1
    {
        const float* qr = g_qkv + (rowBase + w) * QKVW;
        float qv[24];
        float sq = 0.f;
#pragma unroll
        for (int j = 0; j < 24; ++j) {
            qv[j] = qr[lane + 32 * j];
            sq += qv[j] * qv[j];
        }
        sq = warp_sum(sq);
        float invq = 1.0f / fmaxf(sqrtf(sq), 1e-12f);
        float s = 0.f, q2 = 0.f;
#pragma unroll
        for (int j = 0; j < 24; ++j) {
            float tv = qv[j] * invq * kvp[lane + 32 * j];
            s += tv; q2 += tv * tv;
        }
        s = warp_sum(s); q2 = warp_sum(q2);
        if (lane == 0) {
            float mu  = s * (1.f / 768.f);
            float var = q2 * (1.f / 768.f) - mu * mu;
            s_iq[w] = invq;
            s_mu[w] = mu;
            s_rs[w] = rsqrtf(var + 1e-5f);
        }
    }
    __syncthreads();

    // phase 2
    const int rb = blockIdx.x >> 3, mg = blockIdx.x & 7;
    float4* H = reinterpret_cast<float4*>(g_a_hi);
    float4* L = reinterpret_cast<float4*>(g_a_lo);
    for (int i = tid; i < 768; i += 512) {
        int gid = i & 7, kk = (i >> 3) & 1, kt = i >> 4;
        int k0 = kt * 16 + kk * 8;
        const float* r0 = g_qkv + (rowBase + gid) * QKVW + k0;
        const float* r1 = r0 + 8 * QKVW;
        float q0[8], q1[8], kvv[8], gv[8], bv[8];
        *reinterpret_cast<float4*>(q0)      = *reinterpret_cast<const float4*>(r0);
        *reinterpret_cast<float4*>(q0 + 4)  = *reinterpret_cast<const float4*>(r0 + 4);
        *reinterpret_cast<float4*>(q1)      = *reinterpret_cast<const float4*>(r1);
        *reinterpret_cast<float4*>(q1 + 4)  = *reinterpret_cast<const float4*>(r1 + 4);
        *reinterpret_cast<float4*>(kvv)     = *reinterpret_cast<const float4*>(kvp + k0);
        *reinterpret_cast<float4*>(kvv + 4) = *reinterpret_cast<const float4*>(kvp + k0 + 4);
        *reinterpret_cast<float4*>(gv)      = *reinterpret_cast<const float4*>(g + k0);
        *reinterpret_cast<float4*>(gv + 4)  = *reinterpret_cast<const float4*>(g + k0 + 4);
        *reinterpret_cast<float4*>(bv)      = *reinterpret_cast<const float4*>(b + k0);
        *reinterpret_cast<float4*>(bv + 4)  = *reinterpret_cast<const float4*>(b + k0 + 4);
        float iq0 = s_iq[gid], mu0 = s_mu[gid], rs0 = s_rs[gid];
        float iq1 = s_iq[gid + 8], mu1 = s_mu[gid + 8], rs1 = s_rs[gid + 8];
        float h0[8], l0[8], h1[8], l1[8];
#pragma unroll
        for (int j = 0; j < 8; ++j) {
            float2 sp;
            float tv0 = q0[j] * iq0 * kvv[j];
            float tv1 = q1[j] * iq1 * kvv[j];
            sp = split_tf32((tv0 - mu0) * rs0 * gv[j] + bv[j]);
            h0[j] = sp.x; l0[j] = sp.y;
            sp = split_tf32((tv1 - mu1) * rs1 * gv[j] + bv[j]);
            h1[j] = sp.x; l1[j] = sp.y;
        }
        size_t base = ((size_t)(rb * NKT + kt)) * 512 + (mg * 2 + kk) * 32 + gid * 4;
#pragma unroll
        for (int tg = 0; tg < 4; ++tg) {
            H[base + tg] = make_float4(h0[tg], h1[tg], h0[tg + 4], h1[tg + 4]);
            L[base + tg] = make_float4(l0[tg], l1[tg], l0[tg + 4], l1[tg + 4]);
        }
    }
}

// ---------------------------------------------------------------------------
// Launch
// ---------------------------------------------------------------------------
extern "C" void kernel_launch(void* const* d_in, const int* in_sizes, int n_in,
                              void* d_out, int out_size)
{
    (void)in_sizes; (void)n_in; (void)out_size;
    const float* x        = (const float*)d_in[0];
    const float* w_qkv    = (const float*)d_in[1];
    const float* w_proj   = (const float*)d_in[2];
    const float* ln_in_g  = (const float*)d_in[3];
    const float* ln_in_b  = (const float*)d_in[4];
    const float* ln_out_g = (const float*)d_in[5];
    const float* ln_out_b = (const float*)d_in[6];
    float* out = (float*)d_out;

    void *phh, *phl, *pqkv, *pah, *pal, *pwq, *pwp;
    cudaGetSymbolAddress(&phh,  g_h_hi);
    cudaGetSymbolAddress(&phl,  g_h_lo);
    cudaGetSymbolAddress(&pqkv, g_qkv);
    cudaGetSymbolAddress(&pah,  g_a_hi);
    cudaGetSymbolAddress(&pal,  g_a_lo);
    cudaGetSymbolAddress(&pwq,  g_wqkv_pk);
    cudaGetSymbolAddress(&pwp,  g_wproj_pk);

    cudaFuncSetAttribute(tf32x3_gemm_pk_kernel,
                         cudaFuncAttributeMaxDynamicSharedMemorySize,
                         GEMM_SMEM_BYTES);

    {
        int nf4 = NKT * (QKVW / 128) * 1024;     // 884736
        wsplit_pack_kernel<<<(nf4 + 255) / 256, 256>>>(w_qkv, (float*)pwq, QKVW, nf4);
        nf4 = NKT * (CDIM / 128) * 1024;         // 294912
        wsplit_pack_kernel<<<(nf4 + 255) / 256, 256>>>(w_proj, (float*)pwp, CDIM, nf4);
    }

    ln_in_pack_kernel<<<ROWS / 16, 512>>>(x, ln_in_g, ln_in_b);

    tf32x3_gemm_pk_kernel<<<dim3(QKVW / 128, ROWS / 128), 256, GEMM_SMEM_BYTES>>>(
        (const float*)phh, (const float*)phl, (const float*)pwq,
        (float*)pqkv, QKVW);

    invk_kernel<<<ROWS, 192>>>();

    kvpart_kernel<<<dim3(EDIM / 64, NTOK / 512, BATCH), 512>>>();

    kvreduce_kernel<<<(BATCH * EDIM + 255) / 256, 256>>>();

    attn_ln_pack_kernel<<<ROWS / 16, 512>>>(ln_out_g, ln_out_b);

    tf32x3_gemm_pk_kernel<<<dim3(CDIM / 128, ROWS / 128), 256, GEMM_SMEM_BYTES>>>(
        (const float*)pah, (const float*)pal, (const float*)pwp,
        out, CDIM);
}

// round 9
// speedup vs baseline: 2.6075x; 1.8055x over previous
#include <cuda_runtime.h>
#include <cuda_bf16.h>
#include <cstdint>
#include <cstddef>

// ---------------------------------------------------------------------------
// hydra_channel_attention: B=8, N=4096, C=E=768
// GEMMs: mma.sync m16n8k16 bf16 with 3-term (hi*hi + hi*lo + lo*hi)
// error-compensated split. Fragment-packed operand layouts:
//   A packed (hi and lo arrays of uint4): per (rowblk 128, ktile 16):
//     idx = ((rb*NKT+kt)*8 + mg)*32 + lane, uint4 = {a0,a1,a2,a3} bf16x2 regs
//     a0={A[m0][k0+2tg],A[m0][k0+2tg+1]}, a1=rows m0+8, a2/a3 = k+8 pair
//     m0 = rb*128+mg*16+gid, k0 = kt*16, gid=lane>>2, tg=lane&3
//   B packed (uint4): per (colblk 128, ktile 16):
//     idx = ((cb*NKT+kt)*16 + ng)*32 + lane, uint4 = {b0hi,b1hi,b0lo,b1lo}
//     b0={B[k0+2tg][n],B[k0+2tg+1][n]}, b1 = k+8 pair, n = cb*128+ng*8+gid
// -> every fragment read is one conflict-free LDS.128.
// ---------------------------------------------------------------------------

constexpr int BATCH = 8;
constexpr int NTOK  = 4096;
constexpr int CDIM  = 768;
constexpr int EDIM  = 768;
constexpr int ROWS  = BATCH * NTOK;        // 32768
constexpr int QKVW  = 3 * EDIM;            // 2304
constexpr int NCHUNK = 8;
constexpr int NKT   = 48;                  // K/16 (K=768 both GEMMs)

// scratch (device globals; no allocations anywhere)
__device__ uint4 g_h_hi [(size_t)ROWS * CDIM / 8];   // packed bf16 A (GEMM1)
__device__ uint4 g_h_lo [(size_t)ROWS * CDIM / 8];
__device__ float g_qkv  [(size_t)ROWS * QKVW];       // fp32 row-major
__device__ uint4 g_a_hi [(size_t)ROWS * EDIM / 8];   // packed bf16 A (GEMM2)
__device__ uint4 g_a_lo [(size_t)ROWS * EDIM / 8];
__device__ uint4 g_wqkv_pk [(size_t)NKT * (QKVW / 128) * 16 * 32];
__device__ uint4 g_wproj_pk[(size_t)NKT * (CDIM / 128) * 16 * 32];
__device__ float g_invk[ROWS];
__device__ float g_kvpart[NCHUNK * BATCH * EDIM];
__device__ float g_kv  [BATCH * EDIM];

// ---------------------------------------------------------------------------
// helpers
// ---------------------------------------------------------------------------
__device__ __forceinline__ float bf16_round(float x) {
    return __bfloat162float(__float2bfloat16_rn(x));
}
// pack two floats to bf16x2; f_lo -> low half (smaller k), f_hi -> high half
__device__ __forceinline__ uint32_t pack_bf16x2(float f_lo, float f_hi) {
    uint32_t r;
    asm("cvt.rn.bf16x2.f32 %0, %1, %2;" : "=r"(r) : "f"(f_hi), "f"(f_lo));
    return r;
}
__device__ __forceinline__ void mma_bf16(float c[4],
                                         uint32_t a0, uint32_t a1,
                                         uint32_t a2, uint32_t a3,
                                         uint32_t b0, uint32_t b1) {
    asm volatile(
        "mma.sync.aligned.m16n8k16.row.col.f32.bf16.bf16.f32 "
        "{%0,%1,%2,%3}, {%4,%5,%6,%7}, {%8,%9}, {%0,%1,%2,%3};\n"
        : "+f"(c[0]), "+f"(c[1]), "+f"(c[2]), "+f"(c[3])
        : "r"(a0), "r"(a1), "r"(a2), "r"(a3), "r"(b0), "r"(b1));
}
__device__ __forceinline__ void cp16(uint32_t dst_smem, const void* src) {
    asm volatile("cp.async.cg.shared.global [%0], [%1], 16;\n"
                 :: "r"(dst_smem), "l"(src));
}
__device__ __forceinline__ void cp_commit() {
    asm volatile("cp.async.commit_group;\n");
}
template <int N>
__device__ __forceinline__ void cp_wait() {
    asm volatile("cp.async.wait_group %0;\n" :: "n"(N));
}
__device__ __forceinline__ float warp_sum(float v) {
#pragma unroll
    for (int o = 16; o > 0; o >>= 1) v += __shfl_xor_sync(0xffffffffu, v, o);
    return v;
}
__device__ __forceinline__ float2 block_reduce2_192(float a, float b) {
    __shared__ float sa[6], sb[6];
    __syncthreads();
#pragma unroll
    for (int o = 16; o > 0; o >>= 1) {
        a += __shfl_down_sync(0xffffffffu, a, o);
        b += __shfl_down_sync(0xffffffffu, b, o);
    }
    int w = threadIdx.x >> 5;
    if ((threadIdx.x & 31) == 0) { sa[w] = a; sb[w] = b; }
    __syncthreads();
    float ra = 0.f, rb = 0.f;
#pragma unroll
    for (int i = 0; i < 6; ++i) { ra += sa[i]; rb += sb[i]; }
    return make_float2(ra, rb);
}

// ---------------------------------------------------------------------------
// K0: weight split + pack (bf16 hi/lo fragment layout)
// ---------------------------------------------------------------------------
__global__ __launch_bounds__(256) void wsplit_pack_kernel(
    const float* __restrict__ w, uint4* __restrict__ pk, int N, int nf4)
{
    int idx = blockIdx.x * 256 + threadIdx.x;
    if (idx >= nf4) return;
    int lane = idx & 31;
    int t    = idx >> 5;
    int ng   = t & 15;  t >>= 4;
    int kt   = t % NKT;
    int cb   = t / NKT;
    int gid  = lane >> 2, tg = lane & 3;
    int n    = cb * 128 + ng * 8 + gid;
    int k0   = kt * 16 + 2 * tg;

    float w0 = w[(size_t)(k0)     * N + n];
    float w1 = w[(size_t)(k0 + 1) * N + n];
    float w2 = w[(size_t)(k0 + 8) * N + n];
    float w3 = w[(size_t)(k0 + 9) * N + n];
    float h0 = bf16_round(w0), h1 = bf16_round(w1);
    float h2 = bf16_round(w2), h3 = bf16_round(w3);
    uint4 o;
    o.x = pack_bf16x2(h0, h1);
    o.y = pack_bf16x2(h2, h3);
    o.z = pack_bf16x2(w0 - h0, w1 - h1);
    o.w = pack_bf16x2(w2 - h2, w3 - h3);
    pk[idx] = o;
}

// ---------------------------------------------------------------------------
// K1: input LayerNorm -> bf16 split -> packed A layout. Block = 16 rows.
// ---------------------------------------------------------------------------
__global__ __launch_bounds__(512) void ln_in_pack_kernel(
    const float* __restrict__ x,
    const float* __restrict__ g,
    const float* __restrict__ b)
{
    __shared__ float s_mu[16], s_rs[16];
    const int tid = threadIdx.x, w = tid >> 5, lane0 = tid & 31;
    const size_t rowBase = (size_t)blockIdx.x * 16;

    // phase 1: per-row LN stats (warp w -> local row w), fixed-order
    {
        const float* xr = x + (rowBase + w) * CDIM;
        float s = 0.f, q = 0.f;
#pragma unroll
        for (int j = 0; j < 24; ++j) {
            float v = xr[lane0 + 32 * j];
            s += v; q += v * v;
        }
        s = warp_sum(s); q = warp_sum(q);
        if (lane0 == 0) {
            float mu  = s * (1.f / 768.f);
            float var = q * (1.f / 768.f) - mu * mu;
            s_mu[w] = mu;
            s_rs[w] = rsqrtf(var + 1e-5f);
        }
    }
    __syncthreads();

    // phase 2: normalize + split + packed write (48 kt x 32 lanes = 1536)
    const int rb = blockIdx.x >> 3, mg = blockIdx.x & 7;
    for (int i = tid; i < NKT * 32; i += 512) {
        int kt = i >> 5, lane = i & 31;
        int gid = lane >> 2, tg = lane & 3;
        int c0 = kt * 16 + 2 * tg;
        const float* xr0 = x + (rowBase + gid) * CDIM;
        const float* xr1 = xr0 + 8 * CDIM;
        float2 x00 = *reinterpret_cast<const float2*>(xr0 + c0);
        float2 x01 = *reinterpret_cast<const float2*>(xr0 + c0 + 8);
        float2 x10 = *reinterpret_cast<const float2*>(xr1 + c0);
        float2 x11 = *reinterpret_cast<const float2*>(xr1 + c0 + 8);
        float2 gg0 = *reinterpret_cast<const float2*>(g + c0);
        float2 gg1 = *reinterpret_cast<const float2*>(g + c0 + 8);
        float2 bb0 = *reinterpret_cast<const float2*>(b + c0);
        float2 bb1 = *reinterpret_cast<const float2*>(b + c0 + 8);
        float mu0 = s_mu[gid], rs0 = s_rs[gid];
        float mu1 = s_mu[gid + 8], rs1 = s_rs[gid + 8];

        float v0a = (x00.x - mu0) * rs0 * gg0.x + bb0.x;
        float v0b = (x00.y - mu0) * rs0 * gg0.y + bb0.y;
        float v1a = (x10.x - mu1) * rs1 * gg0.x + bb0.x;
        float v1b = (x10.y - mu1) * rs1 * gg0.y + bb0.y;
        float v2a = (x01.x - mu0) * rs0 * gg1.x + bb1.x;
        float v2b = (x01.y - mu0) * rs0 * gg1.y + bb1.y;
        float v3a = (x11.x - mu1) * rs1 * gg1.x + bb1.x;
        float v3b = (x11.y - mu1) * rs1 * gg1.y + bb1.y;

        float h0a = bf16_round(v0a), h0b = bf16_round(v0b);
        float h1a = bf16_round(v1a), h1b = bf16_round(v1b);
        float h2a = bf16_round(v2a), h2b = bf16_round(v2b);
        float h3a = bf16_round(v3a), h3b = bf16_round(v3b);

        uint4 hv, lv;
        hv.x = pack_bf16x2(h0a, h0b);
        hv.y = pack_bf16x2(h1a, h1b);
        hv.z = pack_bf16x2(h2a, h2b);
        hv.w = pack_bf16x2(h3a, h3b);
        lv.x = pack_bf16x2(v0a - h0a, v0b - h0b);
        lv.y = pack_bf16x2(v1a - h1a, v1b - h1b);
        lv.z = pack_bf16x2(v2a - h2a, v2b - h2b);
        lv.w = pack_bf16x2(v3a - h3a, v3b - h3b);

        size_t base = (((size_t)rb * NKT + kt) * 8 + mg) * 32 + lane;
        g_h_hi[base] = hv;
        g_h_lo[base] = lv;
    }
}

// ---------------------------------------------------------------------------
// bf16x3 GEMM on packed operands. C[M,N] row-major.
// Block 128x128, BK=16, 256 threads, 3-stage cp.async, 1 barrier per tile.
// Stage (uint4): Ahi[256] | Alo[256] | B[512]  = 16KB.
// ---------------------------------------------------------------------------
constexpr int STG_U4 = 1024;
constexpr int GEMM_SMEM_BYTES = 3 * STG_U4 * 16;   // 49152

__global__ __launch_bounds__(256, 2) void bf16x3_gemm_kernel(
    const uint4* __restrict__ Ahi, const uint4* __restrict__ Alo,
    const uint4* __restrict__ Bpk, float* __restrict__ C, int N)
{
    extern __shared__ uint4 sm4[];
    const uint32_t smem_u32 = (uint32_t)__cvta_generic_to_shared(sm4);

    const int tid    = threadIdx.x;
    const int lane   = tid & 31;
    const int warpId = tid >> 5;
    const int warpM  = warpId & 3;
    const int warpN  = warpId >> 2;
    const int tg     = lane & 3;
    const int gid    = lane >> 2;

    const int rb = blockIdx.y, cb = blockIdx.x;

    const uint4* gAh = Ahi + (size_t)rb * NKT * 256;
    const uint4* gAl = Alo + (size_t)rb * NKT * 256;
    const uint4* gB  = Bpk + (size_t)cb * NKT * 512;

    float acc[2][8][4];
#pragma unroll
    for (int i = 0; i < 2; ++i)
#pragma unroll
        for (int j = 0; j < 8; ++j)
#pragma unroll
            for (int l = 0; l < 4; ++l) acc[i][j][l] = 0.f;

    auto issue = [&](int kt, int s) {
        const uint32_t base = smem_u32 + (uint32_t)(s * STG_U4 * 16);
        cp16(base + tid * 16,           gAh + kt * 256 + tid);
        cp16(base + 4096 + tid * 16,    gAl + kt * 256 + tid);
        cp16(base + 8192 + tid * 16,    gB + kt * 512 + tid);
        cp16(base + 12288 + tid * 16,   gB + kt * 512 + 256 + tid);
        cp_commit();
    };

    issue(0, 0);
    issue(1, 1);

    int buf = 0;
    for (int t = 0; t < NKT; ++t) {
        if (t + 1 < NKT) cp_wait<1>(); else cp_wait<0>();
        __syncthreads();   // publish tile t; proves buffer (t+2)%3 drained

        if (t + 2 < NKT) issue(t + 2, (buf + 2) % 3);

        const uint4* s4 = sm4 + buf * STG_U4;

        uint4 ah[2], al[2];
#pragma unroll
        for (int ma = 0; ma < 2; ++ma) {
            int fi = (warpM * 2 + ma) * 32 + lane;
            ah[ma] = s4[fi];
            al[ma] = s4[256 + fi];
        }
#pragma unroll
        for (int na = 0; na < 8; ++na) {
            uint4 bv = s4[512 + (warpN * 8 + na) * 32 + lane];
#pragma unroll
            for (int ma = 0; ma < 2; ++ma) {
                mma_bf16(acc[ma][na], ah[ma].x, ah[ma].y, ah[ma].z, ah[ma].w,
                         bv.x, bv.y);
                mma_bf16(acc[ma][na], ah[ma].x, ah[ma].y, ah[ma].z, ah[ma].w,
                         bv.z, bv.w);
                mma_bf16(acc[ma][na], al[ma].x, al[ma].y, al[ma].z, al[ma].w,
                         bv.x, bv.y);
            }
        }
        buf = (buf + 1) % 3;
    }

    // epilogue
#pragma unroll
    for (int ma = 0; ma < 2; ++ma) {
        int r0 = rb * 128 + warpM * 32 + ma * 16 + gid;
#pragma unroll
        for (int na = 0; na < 8; ++na) {
            int col = cb * 128 + warpN * 64 + na * 8 + tg * 2;
            *reinterpret_cast<float2*>(C + (size_t)r0 * N + col) =
                make_float2(acc[ma][na][0], acc[ma][na][1]);
            *reinterpret_cast<float2*>(C + (size_t)(r0 + 8) * N + col) =
                make_float2(acc[ma][na][2], acc[ma][na][3]);
        }
    }
}

// ---------------------------------------------------------------------------
// K3: per-token 1/max(||k||, 1e-12)
// ---------------------------------------------------------------------------
__global__ __launch_bounds__(192) void invk_kernel()
{
    const int row = blockIdx.x;
    const int t   = threadIdx.x;
    const float4 v =
        reinterpret_cast<const float4*>(g_qkv + (size_t)row * QKVW + EDIM)[t];
    float sq = v.x * v.x + v.y * v.y + v.z * v.z + v.w * v.w;
    float2 r = block_reduce2_192(sq, 0.f);
    if (t == 0) g_invk[row] = 1.0f / fmaxf(sqrtf(r.x), 1e-12f);
}

// ---------------------------------------------------------------------------
// K4: partial kv over 512-token chunks (fixed-order, deterministic)
// ---------------------------------------------------------------------------
__global__ __launch_bounds__(512) void kvpart_kernel()
{
    const int el = threadIdx.x & 63;
    const int ng = threadIdx.x >> 6;
    const int e  = blockIdx.x * 64 + el;
    const int b  = blockIdx.z;
    const int nBase = blockIdx.y * 512;

    float s = 0.f;
#pragma unroll 4
    for (int i = 0; i < 64; ++i) {
        int n = nBase + i * 8 + ng;
        size_t row = (size_t)b * NTOK + n;
        const float* p = g_qkv + row * QKVW;
        s += p[EDIM + e] * g_invk[row] * p[2 * EDIM + e];
    }
    __shared__ float red[8][64];
    red[ng][el] = s;
    __syncthreads();
    if (ng == 0) {
        float tot = 0.f;
#pragma unroll
        for (int c = 0; c < 8; ++c) tot += red[c][el];
        g_kvpart[(blockIdx.y * BATCH + b) * EDIM + e] = tot;
    }
}

__global__ __launch_bounds__(256) void kvreduce_kernel()
{
    int idx = blockIdx.x * 256 + threadIdx.x;
    if (idx < BATCH * EDIM) {
        float s = 0.f;
#pragma unroll
        for (int c = 0; c < NCHUNK; ++c) s += g_kvpart[c * BATCH * EDIM + idx];
        g_kv[idx] = s;
    }
}

// ---------------------------------------------------------------------------
// K6: fused invq + attn + output LayerNorm -> bf16 split -> packed A.
// Block = 16 rows, 512 threads.
// ---------------------------------------------------------------------------
__global__ __launch_bounds__(512) void attn_ln_pack_kernel(
    const float* __restrict__ g,
    const float* __restrict__ b)
{
    __shared__ float s_iq[16], s_mu[16], s_rs[16];
    const int tid = threadIdx.x, w = tid >> 5, lane0 = tid & 31;
    const size_t rowBase = (size_t)blockIdx.x * 16;
    const int bat = (int)(rowBase >> 12);
    const float* kvp = g_kv + bat * EDIM;

    // phase 1: per-row invq + LN stats of tv = q*invq*kv
    {
        const float* qr = g_qkv + (rowBase + w) * QKVW;
        float qv[24];
        float sq = 0.f;
#pragma unroll
        for (int j = 0; j < 24; ++j) {
            qv[j] = qr[lane0 + 32 * j];
            sq += qv[j] * qv[j];
        }
        sq = warp_sum(sq);
        float invq = 1.0f / fmaxf(sqrtf(sq), 1e-12f);
        float s = 0.f, q2 = 0.f;
#pragma unroll
        for (int j = 0; j < 24; ++j) {
            float tv = qv[j] * invq * kvp[lane0 + 32 * j];
            s += tv; q2 += tv * tv;
        }
        s = warp_sum(s); q2 = warp_sum(q2);
        if (lane0 == 0) {
            float mu  = s * (1.f / 768.f);
            float var = q2 * (1.f / 768.f) - mu * mu;
            s_iq[w] = invq;
            s_mu[w] = mu;
            s_rs[w] = rsqrtf(var + 1e-5f);
        }
    }
    __syncthreads();

    // phase 2
    const int rb = blockIdx.x >> 3, mg = blockIdx.x & 7;
    for (int i = tid; i < NKT * 32; i += 512) {
        int kt = i >> 5, lane = i & 31;
        int gid = lane >> 2, tg = lane & 3;
        int c0 = kt * 16 + 2 * tg;
        const float* qr0 = g_qkv + (rowBase + gid) * QKVW;
        const float* qr1 = qr0 + 8 * QKVW;
        float2 q00 = *reinterpret_cast<const float2*>(qr0 + c0);
        float2 q01 = *reinterpret_cast<const float2*>(qr0 + c0 + 8);
        float2 q10 = *reinterpret_cast<const float2*>(qr1 + c0);
        float2 q11 = *reinterpret_cast<const float2*>(qr1 + c0 + 8);
        float2 kv0 = *reinterpret_cast<const float2*>(kvp + c0);
        float2 kv1 = *reinterpret_cast<const float2*>(kvp + c0 + 8);
        float2 gg0 = *reinterpret_cast<const float2*>(g + c0);
        float2 gg1 = *reinterpret_cast<const float2*>(g + c0 + 8);
        float2 bb0 = *reinterpret_cast<const float2*>(b + c0);
        float2 bb1 = *reinterpret_cast<const float2*>(b + c0 + 8);
        float iq0 = s_iq[gid], mu0 = s_mu[gid], rs0 = s_rs[gid];
        float iq1 = s_iq[gid + 8], mu1 = s_mu[gid + 8], rs1 = s_rs[gid + 8];

        float v0a = (q00.x * iq0 * kv0.x - mu0) * rs0 * gg0.x + bb0.x;
        float v0b = (q00.y * iq0 * kv0.y - mu0) * rs0 * gg0.y + bb0.y;
        float v1a = (q10.x * iq1 * kv0.x - mu1) * rs1 * gg0.x + bb0.x;
        float v1b = (q10.y * iq1 * kv0.y - mu1) * rs1 * gg0.y + bb0.y;
        float v2a = (q01.x * iq0 * kv1.x - mu0) * rs0 * gg1.x + bb1.x;
        float v2b = (q01.y * iq0 * kv1.y - mu0) * rs0 * gg1.y + bb1.y;
        float v3a = (q11.x * iq1 * kv1.x - mu1) * rs1 * gg1.x + bb1.x;
        float v3b = (q11.y * iq1 * kv1.y - mu1) * rs1 * gg1.y + bb1.y;

        float h0a = bf16_round(v0a), h0b = bf16_round(v0b);
        float h1a = bf16_round(v1a), h1b = bf16_round(v1b);
        float h2a = bf16_round(v2a), h2b = bf16_round(v2b);
        float h3a = bf16_round(v3a), h3b = bf16_round(v3b);

        uint4 hv, lv;
        hv.x = pack_bf16x2(h0a, h0b);
        hv.y = pack_bf16x2(h1a, h1b);
        hv.z = pack_bf16x2(h2a, h2b);
        hv.w = pack_bf16x2(h3a, h3b);
        lv.x = pack_bf16x2(v0a - h0a, v0b - h0b);
        lv.y = pack_bf16x2(v1a - h1a, v1b - h1b);
        lv.z = pack_bf16x2(v2a - h2a, v2b - h2b);
        lv.w = pack_bf16x2(v3a - h3a, v3b - h3b);

        size_t base = (((size_t)rb * NKT + kt) * 8 + mg) * 32 + lane;
        g_a_hi[base] = hv;
        g_a_lo[base] = lv;
    }
}

// ---------------------------------------------------------------------------
// Launch
// ---------------------------------------------------------------------------
extern "C" void kernel_launch(void* const* d_in, const int* in_sizes, int n_in,
                              void* d_out, int out_size)
{
    (void)in_sizes; (void)n_in; (void)out_size;
    const float* x        = (const float*)d_in[0];
    const float* w_qkv    = (const float*)d_in[1];
    const float* w_proj   = (const float*)d_in[2];
    const float* ln_in_g  = (const float*)d_in[3];
    const float* ln_in_b  = (const float*)d_in[4];
    const float* ln_out_g = (const float*)d_in[5];
    const float* ln_out_b = (const float*)d_in[6];
    float* out = (float*)d_out;

    void *phh, *phl, *pqkv, *pah, *pal, *pwq, *pwp;
    cudaGetSymbolAddress(&phh,  g_h_hi);
    cudaGetSymbolAddress(&phl,  g_h_lo);
    cudaGetSymbolAddress(&pqkv, g_qkv);
    cudaGetSymbolAddress(&pah,  g_a_hi);
    cudaGetSymbolAddress(&pal,  g_a_lo);
    cudaGetSymbolAddress(&pwq,  g_wqkv_pk);
    cudaGetSymbolAddress(&pwp,  g_wproj_pk);

    cudaFuncSetAttribute(bf16x3_gemm_kernel,
                         cudaFuncAttributeMaxDynamicSharedMemorySize,
                         GEMM_SMEM_BYTES);

    {
        int nf4 = NKT * (QKVW / 128) * 16 * 32;   // 442368
        wsplit_pack_kernel<<<(nf4 + 255) / 256, 256>>>(
            w_qkv, (uint4*)pwq, QKVW, nf4);
        nf4 = NKT * (CDIM / 128) * 16 * 32;       // 147456
        wsplit_pack_kernel<<<(nf4 + 255) / 256, 256>>>(
            w_proj, (uint4*)pwp, CDIM, nf4);
    }

    ln_in_pack_kernel<<<ROWS / 16, 512>>>(x, ln_in_g, ln_in_b);

    bf16x3_gemm_kernel<<<dim3(QKVW / 128, ROWS / 128), 256, GEMM_SMEM_BYTES>>>(
        (const uint4*)phh, (const uint4*)phl, (const uint4*)pwq,
        (float*)pqkv, QKVW);

    invk_kernel<<<ROWS, 192>>>();

    kvpart_kernel<<<dim3(EDIM / 64, NTOK / 512, BATCH), 512>>>();

    kvreduce_kernel<<<(BATCH * EDIM + 255) / 256, 256>>>();

    attn_ln_pack_kernel<<<ROWS / 16, 512>>>(ln_out_g, ln_out_b);

    bf16x3_gemm_kernel<<<dim3(CDIM / 128, ROWS / 128), 256, GEMM_SMEM_BYTES>>>(
        (const uint4*)pah, (const uint4*)pal, (const uint4*)pwp,
        out, CDIM);
}